// round 16
// baseline (speedup 1.0000x reference)
#include <cuda_runtime.h>
#include <cuda_bf16.h>
#include <cstdint>

#define BB    128
#define TBODY 512
#define TPUN  256
#define EMBD  300
#define HD    64
#define NG    256      // 4H gates per direction
#define NC    512      // both directions stacked
#define KP2   320      // K padded to multiple of 32 for bf16 MMA

typedef unsigned long long u64;
typedef unsigned int u32;

// ---------------- f32x2 packed-FMA helpers (FFMA2 via PTX) ----------------
__device__ __forceinline__ u64 pk2(float lo, float hi){
    u64 r; asm("mov.b64 %0, {%1,%2};" : "=l"(r) : "f"(lo), "f"(hi)); return r;
}
__device__ __forceinline__ float2 upk2(u64 v){
    float2 r; asm("mov.b64 {%0,%1}, %2;" : "=f"(r.x), "=f"(r.y) : "l"(v)); return r;
}
__device__ __forceinline__ u64 fma2(u64 a, u64 b, u64 c){
    u64 d; asm("fma.rn.f32x2 %0, %1, %2, %3;" : "=l"(d) : "l"(a), "l"(b), "l"(c)); return d;
}

// ---------------- MMA helpers ----------------
__device__ __forceinline__ u32 s2u(const void* p){
    return (u32)__cvta_generic_to_shared(p);
}
__device__ __forceinline__ void ldsm_x4(u32& r0, u32& r1, u32& r2, u32& r3, u32 addr){
    asm volatile("ldmatrix.sync.aligned.m8n8.x4.shared.b16 {%0,%1,%2,%3}, [%4];"
                 : "=r"(r0), "=r"(r1), "=r"(r2), "=r"(r3) : "r"(addr));
}
__device__ __forceinline__ void ldsm_x4t(u32& r0, u32& r1, u32& r2, u32& r3, u32 addr){
    asm volatile("ldmatrix.sync.aligned.m8n8.x4.trans.shared.b16 {%0,%1,%2,%3}, [%4];"
                 : "=r"(r0), "=r"(r1), "=r"(r2), "=r"(r3) : "r"(addr));
}
__device__ __forceinline__ void mma_bf16(float* c, const u32* a, const u32* b){
    asm volatile("mma.sync.aligned.m16n8k16.row.col.f32.bf16.bf16.f32 "
                 "{%0,%1,%2,%3}, {%4,%5,%6,%7}, {%8,%9}, {%0,%1,%2,%3};"
                 : "+f"(c[0]), "+f"(c[1]), "+f"(c[2]), "+f"(c[3])
                 : "r"(a[0]), "r"(a[1]), "r"(a[2]), "r"(a[3]), "r"(b[0]), "r"(b[1]));
}

// ---------------- scratch (static device globals; no allocation) ----------------
__device__ float          g_xp_body[(size_t)BB*TBODY*NC];
__device__ float          g_xp_pun [(size_t)BB*TPUN *NC];
__device__ __nv_bfloat16  g_Wth[2][(size_t)KP2*NC];   // Wih^T hi (k-major, zero-padded)
__device__ __nv_bfloat16  g_Wtl[2][(size_t)KP2*NC];   // Wih^T lo
__device__ float          g_biasv[2][NC];
__device__ int            g_lens[2][BB];
__device__ float          g_bodyM[(size_t)BB*TBODY*128];
__device__ float          g_punM [(size_t)BB*TPUN *128];
__device__ float          g_Ab[BB*TBODY];
__device__ float          g_Bp[BB*TPUN];
__device__ float          g_rowmax[BB*TBODY];
__device__ unsigned       g_colmax[BB*TPUN];
__device__ float          g_feat[BB*256];

// ---------------- helpers ----------------
__device__ __forceinline__ float sigm(float x){ return 1.f/(1.f + __expf(-x)); }
__device__ __forceinline__ float tanh_fast(float x){
    x = fminf(fmaxf(x, -15.f), 15.f);
    float t = __expf(2.f*x);
    return (t - 1.f)/(t + 1.f);
}
__device__ __forceinline__ unsigned fmap(float f){
    unsigned u = __float_as_uint(f);
    return (u & 0x80000000u) ? ~u : (u | 0x80000000u);
}
__device__ __forceinline__ float funmap(unsigned u){
    return (u & 0x80000000u) ? __uint_as_float(u ^ 0x80000000u) : __uint_as_float(~u);
}

// ---------------- zero-init of masked output buffers ----------------
__global__ void k_zero(){
    size_t i = (size_t)blockIdx.x*blockDim.x + threadIdx.x;
    size_t stride = (size_t)gridDim.x*blockDim.x;
    for (size_t k=i; k<(size_t)BB*TBODY*128; k+=stride) g_bodyM[k] = 0.f;
    for (size_t k=i; k<(size_t)BB*TPUN *128; k+=stride) g_punM [k] = 0.f;
    for (size_t k=i; k<(size_t)BB*TPUN;      k+=stride) g_colmax[k] = 0u;
}

// ---------------- sequence lengths ----------------
__global__ void k_lens(const int* __restrict__ body_idx, const int* __restrict__ pun_idx){
    int c = blockIdx.y, b = blockIdx.x;
    int T = c ? TPUN : TBODY;
    const int* a = (c ? pun_idx : body_idx) + (size_t)b*T;
    int tid = threadIdx.x;
    int cnt = 0;
    for (int t = tid; t < T; t += 256) cnt += (a[t] != 0);
    #pragma unroll
    for (int o=16;o;o>>=1) cnt += __shfl_xor_sync(0xffffffffu, cnt, o);
    __shared__ int sred[8];
    if ((tid & 31) == 0) sred[tid>>5] = cnt;
    __syncthreads();
    if (tid == 0){
        int s = 0;
        #pragma unroll
        for (int i=0;i<8;i++) s += sred[i];
        g_lens[c][b] = s;
    }
}

// ---------------- prepack Wih^T to bf16 hi/lo (k-major, zero-padded) + bias ------
__global__ void k_prep(const float* __restrict__ bWf, const float* __restrict__ bWb,
                       const float* __restrict__ pWf, const float* __restrict__ pWb,
                       const float* __restrict__ bbf, const float* __restrict__ bbb,
                       const float* __restrict__ pbf, const float* __restrict__ pbb){
    int gid = blockIdx.x*256 + threadIdx.x;
    const int tot = 2*KP2*NC;
    if (gid < tot){
        int c = gid / (KP2*NC);
        int r = gid % (KP2*NC);
        int k = r / NC, n = r % NC;
        float v = 0.f;
        if (k < EMBD){
            const float* W = c ? (n < NG ? pWf : pWb) : (n < NG ? bWf : bWb);
            v = W[(n & 255)*EMBD + k];
        }
        __nv_bfloat16 h = __float2bfloat16(v);
        __nv_bfloat16 l = __float2bfloat16(v - __bfloat162float(h));
        g_Wth[c][(size_t)k*NC + n] = h;
        g_Wtl[c][(size_t)k*NC + n] = l;
    }
    if (gid < 2*NC){
        int c = gid / NC, n = gid % NC;
        const float* bi = c ? (n < NG ? pbf : pbb) : (n < NG ? bbf : bbb);
        g_biasv[c][n] = bi[n & 255];
    }
}

// ---------------- gather + projection GEMM via mma.sync bf16 split --------------
// Block 128m x 64n. 8 warps as 4m x 2n; warp tile 32x32 = 2 m16 x 4 n8 mma tiles.
// acc = Ah*Bh + Ah*Bl + Al*Bh  (2-term split-bf16, fp32 accumulate)
// A gather is row-coalesced: thread (row=tid>>3, kq=(tid&7)*4) loads float4.
__global__ __launch_bounds__(256,2) void k_gemm3(const int* __restrict__ body_idx,
                                                 const int* __restrict__ pun_idx,
                                                 const float* __restrict__ emb){
    __shared__ __align__(16) __nv_bfloat16 Ah[128][40];   // 32 k + pad 8
    __shared__ __align__(16) __nv_bfloat16 Al[128][40];
    __shared__ __align__(16) __nv_bfloat16 Bh[32][72];    // 64 n + pad 8
    __shared__ __align__(16) __nv_bfloat16 Bl[32][72];

    int bid = blockIdx.x;
    int corpus = (bid >= 4096);
    int local = corpus ? bid - 4096 : bid;
    int mt = local >> 3, nt = local & 7;
    int m0 = mt*128, n0 = nt*64;

    const int*   idx  = corpus ? pun_idx : body_idx;
    float*       out  = corpus ? g_xp_pun : g_xp_body;
    const __nv_bfloat16* WtH = g_Wth[corpus];
    const __nv_bfloat16* WtL = g_Wtl[corpus];
    const float* bias = g_biasv[corpus];

    int tid  = threadIdx.x;
    int lane = tid & 31, warp = tid >> 5;
    int warp_m = warp & 3, warp_n = warp >> 2;     // 4 x 2 warps
    int wm0 = warp_m*32, wn0 = warp_n*32;

    // A staging roles (coalesced): 4 passes of 32 rows; 8 threads x float4 per row
    int arow4 = tid >> 3;          // 0..31 (row within pass)
    int kq    = (tid & 7)*4;       // 0..28 (k offset within 32-k tile)
    const float* aptr[4];
    #pragma unroll
    for (int p=0;p<4;p++)
        aptr[p] = emb + (size_t)idx[m0 + p*32 + arow4]*EMBD + kq;

    // B staging roles
    int br = tid >> 3;              // B row (k) 0..31
    int bc = (tid & 7)*8;           // B col group (8 bf16)

    float acc[2][4][4];
    #pragma unroll
    for (int i=0;i<2;i++)
        #pragma unroll
        for (int j=0;j<4;j++)
            #pragma unroll
            for (int q=0;q<4;q++) acc[i][j][q] = 0.f;

    for (int k0=0; k0<KP2; k0+=32){
        __syncthreads();
        {   // stage A: coalesced float4 gather -> bf16 hi/lo
            #pragma unroll
            for (int p=0;p<4;p++){
                int row = p*32 + arow4;
                const float* src = aptr[p] + k0;
                float4 v;
                if (k0 + kq + 3 < EMBD){
                    v = *(const float4*)src;
                } else {
                    v.x = (k0+kq   < EMBD) ? src[0] : 0.f;
                    v.y = (k0+kq+1 < EMBD) ? src[1] : 0.f;
                    v.z = (k0+kq+2 < EMBD) ? src[2] : 0.f;
                    v.w = (k0+kq+3 < EMBD) ? src[3] : 0.f;
                }
                __nv_bfloat16 h0=__float2bfloat16(v.x), h1=__float2bfloat16(v.y);
                __nv_bfloat16 h2=__float2bfloat16(v.z), h3=__float2bfloat16(v.w);
                __nv_bfloat162 hh0=__halves2bfloat162(h0,h1);
                __nv_bfloat162 hh1=__halves2bfloat162(h2,h3);
                __nv_bfloat162 ll0=__halves2bfloat162(
                    __float2bfloat16(v.x-__bfloat162float(h0)),
                    __float2bfloat16(v.y-__bfloat162float(h1)));
                __nv_bfloat162 ll1=__halves2bfloat162(
                    __float2bfloat16(v.z-__bfloat162float(h2)),
                    __float2bfloat16(v.w-__bfloat162float(h3)));
                *(uint2*)&Ah[row][kq] = make_uint2(*(u32*)&hh0, *(u32*)&hh1);
                *(uint2*)&Al[row][kq] = make_uint2(*(u32*)&ll0, *(u32*)&ll1);
            }
        }
        {   // stage B: direct bf16 copy (prepacked)
            size_t src = (size_t)(k0 + br)*NC + n0 + bc;
            *(uint4*)&Bh[br][bc] = *(const uint4*)&WtH[src];
            *(uint4*)&Bl[br][bc] = *(const uint4*)&WtL[src];
        }
        __syncthreads();

        #pragma unroll
        for (int ks=0; ks<2; ks++){
            int kb = ks*16;
            // A fragments (hi & lo) for 2 m-tiles
            u32 ah[2][4], al[2][4];
            int arowf = (lane & 15);
            int acolf = kb + ((lane >> 4) << 3);
            #pragma unroll
            for (int mi=0; mi<2; mi++){
                u32 aAddrH = s2u(&Ah[wm0 + mi*16 + arowf][acolf]);
                ldsm_x4(ah[mi][0], ah[mi][1], ah[mi][2], ah[mi][3], aAddrH);
                u32 aAddrL = s2u(&Al[wm0 + mi*16 + arowf][acolf]);
                ldsm_x4(al[mi][0], al[mi][1], al[mi][2], al[mi][3], aAddrL);
            }
            // B fragments (hi & lo) for 4 n-tiles (2 per ldmatrix.x4.trans)
            u32 bh[4][2], bl[4][2];
            int bkrow = kb + (lane & 15);
            #pragma unroll
            for (int nh=0; nh<2; nh++){
                int bncol = wn0 + nh*16 + ((lane & 16) ? 8 : 0);
                u32 r0,r1,r2,r3;
                ldsm_x4t(r0, r1, r2, r3, s2u(&Bh[bkrow][bncol]));
                bh[2*nh][0]=r0; bh[2*nh][1]=r1; bh[2*nh+1][0]=r2; bh[2*nh+1][1]=r3;
                ldsm_x4t(r0, r1, r2, r3, s2u(&Bl[bkrow][bncol]));
                bl[2*nh][0]=r0; bl[2*nh][1]=r1; bl[2*nh+1][0]=r2; bl[2*nh+1][1]=r3;
            }
            // 2-term split: hh + hl + lh
            #pragma unroll
            for (int mi=0; mi<2; mi++)
                #pragma unroll
                for (int ni=0; ni<4; ni++){
                    mma_bf16(acc[mi][ni], ah[mi], bh[ni]);
                    mma_bf16(acc[mi][ni], ah[mi], bl[ni]);
                    mma_bf16(acc[mi][ni], al[mi], bh[ni]);
                }
        }
    }

    // epilogue: bias + store (c0,c1 -> row r4; c2,c3 -> row r4+8)
    int r4 = lane >> 2, c2 = (lane & 3)*2;
    #pragma unroll
    for (int mi=0; mi<2; mi++){
        #pragma unroll
        for (int ni=0; ni<4; ni++){
            int n = n0 + wn0 + ni*8 + c2;
            float b0 = bias[n], b1 = bias[n+1];
            int m = m0 + wm0 + mi*16 + r4;
            float2 o0 = make_float2(acc[mi][ni][0] + b0, acc[mi][ni][1] + b1);
            float2 o1 = make_float2(acc[mi][ni][2] + b0, acc[mi][ni][3] + b1);
            *(float2*)&out[(size_t)m*NC + n]       = o0;
            *(float2*)&out[(size_t)(m+8)*NC + n]   = o1;
        }
    }
}

// ---------------- LSTM recurrence: 1 block per (corpus,batch,dir), f32x2 dots ----
__global__ __launch_bounds__(256) void k_scan(const float* __restrict__ bWhhf,
                                              const float* __restrict__ bWhhb,
                                              const float* __restrict__ pWhhf,
                                              const float* __restrict__ pWhhb){
    int bid = blockIdx.x;
    int corpus = bid >> 8;
    int b   = (bid & 255) >> 1;
    int dir = bid & 1;
    int T   = corpus ? TPUN : TBODY;
    int len = g_lens[corpus][b];
    const float* Whh = corpus ? (dir ? pWhhb : pWhhf) : (dir ? bWhhb : bWhhf);
    const float* xp  = corpus ? g_xp_pun : g_xp_body;
    float* M         = corpus ? g_punM   : g_bodyM;

    int tid = threadIdx.x;
    int j = tid >> 2, ssub = tid & 3;

    u64 Wr2[4][8];
    #pragma unroll
    for (int q=0;q<4;q++){
        const u64* wp = (const u64*)(Whh + (size_t)(q*64 + j)*64 + ssub*16);
        #pragma unroll
        for (int kk=0;kk<8;kk++) Wr2[q][kk] = wp[kk];
    }

    __shared__ __align__(16) float hbuf[2][64];
    __shared__ float xps[2][256];
    if (tid < 64) hbuf[0][tid] = 0.f;
    if (len > 0){
        int r0 = b*T + (dir ? (len-1) : 0);
        xps[0][tid] = xp[(size_t)r0*NC + dir*NG + tid];
    }
    __syncthreads();

    float c = 0.f;
    for (int s=0; s<len; s++){
        int cur = s & 1;
        float xn = 0.f;
        if (s+1 < len){
            int t1 = dir ? (len-2-s) : (s+1);
            xn = xp[(size_t)(b*T + t1)*NC + dir*NG + tid];
        }
        ulonglong2 hq0 = *(const ulonglong2*)&hbuf[cur][ssub*16];
        ulonglong2 hq1 = *(const ulonglong2*)&hbuf[cur][ssub*16+4];
        ulonglong2 hq2 = *(const ulonglong2*)&hbuf[cur][ssub*16+8];
        ulonglong2 hq3 = *(const ulonglong2*)&hbuf[cur][ssub*16+12];
        u64 h2[8] = {hq0.x,hq0.y,hq1.x,hq1.y,hq2.x,hq2.y,hq3.x,hq3.y};
        u64 s0=0ull, s1=0ull, s2=0ull, s3=0ull;
        #pragma unroll
        for (int kk=0;kk<8;kk++){
            s0 = fma2(h2[kk], Wr2[0][kk], s0);
            s1 = fma2(h2[kk], Wr2[1][kk], s1);
            s2 = fma2(h2[kk], Wr2[2][kk], s2);
            s3 = fma2(h2[kk], Wr2[3][kk], s3);
        }
        float2 f0=upk2(s0), f1=upk2(s1), f2=upk2(s2), f3=upk2(s3);
        float a0=f0.x+f0.y, a1=f1.x+f1.y, a2=f2.x+f2.y, a3=f3.x+f3.y;
        #pragma unroll
        for (int o=1;o<=2;o<<=1){
            a0 += __shfl_xor_sync(0xffffffffu, a0, o);
            a1 += __shfl_xor_sync(0xffffffffu, a1, o);
            a2 += __shfl_xor_sync(0xffffffffu, a2, o);
            a3 += __shfl_xor_sync(0xffffffffu, a3, o);
        }
        float gi = sigm     (a0 + xps[cur][      j]);
        float gf = sigm     (a1 + xps[cur][ 64 + j]);
        float gg = tanh_fast(a2 + xps[cur][128 + j]);
        float go = sigm     (a3 + xps[cur][192 + j]);
        c = gf*c + gi*gg;
        float hn = go * tanh_fast(c);
        if (ssub == 0){
            hbuf[cur^1][j] = hn;
            int tout = dir ? (len-1-s) : s;
            M[((size_t)(b*T + tout))*128 + dir*64 + j] = hn;
        }
        xps[cur^1][tid] = xn;
        __syncthreads();
    }
}

// ---------------- row dots: A[t]=body_M.w1, Bv[p]=pun_M.w2 (1 warp per row) ----------------
__global__ void k_rowdots(const float* __restrict__ wu){
    int gwarp = (blockIdx.x*256 + threadIdx.x) >> 5;
    int lane  = threadIdx.x & 31;
    const float* M; const float* w; float* o;
    if (gwarp < BB*TBODY){
        M = g_bodyM + (size_t)gwarp*128; w = wu;       o = g_Ab + gwarp;
    } else {
        int r = gwarp - BB*TBODY;
        if (r >= BB*TPUN) return;
        M = g_punM  + (size_t)r*128;     w = wu + 128; o = g_Bp + r;
    }
    float s = 0.f;
    #pragma unroll
    for (int i=0;i<4;i++) s += M[lane + 32*i]*w[lane + 32*i];
    #pragma unroll
    for (int off=16;off;off>>=1) s += __shfl_xor_sync(0xffffffffu, s, off);
    if (lane == 0) *o = s;
}

// ---------------- alignment maxes: 64t x 256p tile, k-major body, quad-split p --
__global__ __launch_bounds__(256) void k_align(const float* __restrict__ wu){
    __shared__ __align__(16) float bst[16][68];   // body chunk, k-major (x w3)
    __shared__ __align__(16) float ps[16][256];   // pun k-chunk; reused as colred
    __shared__ float As_[64];
    __shared__ float Bps[256];
    int b = blockIdx.y;
    int t0 = blockIdx.x*64;
    int tid = threadIdx.x;
    int ty = tid >> 5, tx = tid & 31;

    if (tid < 64) As_[tid] = g_Ab[b*TBODY + t0 + tid];
    Bps[tid] = g_Bp[b*TPUN + tid];

    u64 acc2[8][4];
    #pragma unroll
    for (int i=0;i<8;i++)
        #pragma unroll
        for (int j=0;j<4;j++) acc2[i][j] = 0ull;

    for (int kc=0;kc<128;kc+=16){
        __syncthreads();
        {   // stage pun chunk (transposed: ps[k][p])
            const float* src = g_punM + ((size_t)(b*TPUN + tid))*128 + kc;
            float4 v0 = *(const float4*)(src   );
            float4 v1 = *(const float4*)(src+ 4);
            float4 v2 = *(const float4*)(src+ 8);
            float4 v3 = *(const float4*)(src+12);
            ps[ 0][tid]=v0.x; ps[ 1][tid]=v0.y; ps[ 2][tid]=v0.z; ps[ 3][tid]=v0.w;
            ps[ 4][tid]=v1.x; ps[ 5][tid]=v1.y; ps[ 6][tid]=v1.z; ps[ 7][tid]=v1.w;
            ps[ 8][tid]=v2.x; ps[ 9][tid]=v2.y; ps[10][tid]=v2.z; ps[11][tid]=v2.w;
            ps[12][tid]=v3.x; ps[13][tid]=v3.y; ps[14][tid]=v3.z; ps[15][tid]=v3.w;
        }
        {   // stage body chunk k-major (x w3): bst[k][t]
            int t = tid >> 2, kq2 = (tid & 3)*4;
            const float* src = g_bodyM + ((size_t)(b*TBODY + t0 + t))*128 + kc + kq2;
            float4 v = *(const float4*)src;
            v.x *= wu[256+kc+kq2];   v.y *= wu[256+kc+kq2+1];
            v.z *= wu[256+kc+kq2+2]; v.w *= wu[256+kc+kq2+3];
            bst[kq2  ][t] = v.x; bst[kq2+1][t] = v.y;
            bst[kq2+2][t] = v.z; bst[kq2+3][t] = v.w;
        }
        __syncthreads();
        #pragma unroll
        for (int kk=0;kk<16;kk++){
            float4 tv0 = *(const float4*)&bst[kk][ty*8];
            float4 tv1 = *(const float4*)&bst[kk][ty*8+4];
            ulonglong2 p0 = *(const ulonglong2*)&ps[kk][tx*4];
            ulonglong2 p1 = *(const ulonglong2*)&ps[kk][tx*4+128];
            u64 p2[4] = {p0.x, p0.y, p1.x, p1.y};
            float tv[8] = {tv0.x,tv0.y,tv0.z,tv0.w, tv1.x,tv1.y,tv1.z,tv1.w};
            #pragma unroll
            for (int it=0;it<8;it++){
                u64 ar = pk2(tv[it], tv[it]);
                #pragma unroll
                for (int c=0;c<4;c++) acc2[it][c] = fma2(ar, p2[c], acc2[it][c]);
            }
        }
    }
    float Bloc[8];
    #pragma unroll
    for (int q=0;q<4;q++){ Bloc[q] = Bps[tx*4+q]; Bloc[4+q] = Bps[tx*4+128+q]; }
    #pragma unroll
    for (int it=0;it<8;it++){
        float m = -3.4e38f;
        #pragma unroll
        for (int jj=0;jj<4;jj++){
            float2 v = upk2(acc2[it][jj]);
            m = fmaxf(m, v.x + Bloc[2*jj]);
            m = fmaxf(m, v.y + Bloc[2*jj+1]);
        }
        #pragma unroll
        for (int off=16;off;off>>=1) m = fmaxf(m, __shfl_xor_sync(0xffffffffu, m, off));
        if (tx == 0) g_rowmax[b*TBODY + t0 + ty*8 + it] = As_[ty*8+it] + m;
    }
    __syncthreads();
    float (*colred)[256] = (float(*)[256])ps;
    #pragma unroll
    for (int jj=0;jj<4;jj++){
        float mx_lo = -3.4e38f, mx_hi = -3.4e38f;
        #pragma unroll
        for (int it=0;it<8;it++){
            float2 v = upk2(acc2[it][jj]);
            mx_lo = fmaxf(mx_lo, v.x + As_[ty*8+it]);
            mx_hi = fmaxf(mx_hi, v.y + As_[ty*8+it]);
        }
        int pl = (jj < 2) ? (tx*4 + 2*jj) : (tx*4 + 128 + 2*(jj-2));
        colred[ty][pl    ] = mx_lo;
        colred[ty][pl + 1] = mx_hi;
    }
    __syncthreads();
    {
        float m = colred[0][tid];
        #pragma unroll
        for (int r=1;r<8;r++) m = fmaxf(m, colred[r][tid]);
        atomicMax(&g_colmax[b*TPUN + tid], fmap(m));
    }
}

// ---------------- block reduce helpers via smem ----------------
__device__ __forceinline__ float block_reduce_max(float v, float* red8, int tid){
    #pragma unroll
    for (int o=16;o;o>>=1) v = fmaxf(v, __shfl_xor_sync(0xffffffffu, v, o));
    if ((tid & 31) == 0) red8[tid>>5] = v;
    __syncthreads();
    if (tid == 0){
        float x = red8[0];
        #pragma unroll
        for (int i=1;i<8;i++) x = fmaxf(x, red8[i]);
        red8[0] = x;
    }
    __syncthreads();
    float r = red8[0];
    __syncthreads();
    return r;
}
__device__ __forceinline__ float block_reduce_sum(float v, float* red8, int tid){
    #pragma unroll
    for (int o=16;o;o>>=1) v += __shfl_xor_sync(0xffffffffu, v, o);
    if ((tid & 31) == 0) red8[tid>>5] = v;
    __syncthreads();
    if (tid == 0){
        float x = 0.f;
        #pragma unroll
        for (int i=0;i<8;i++) x += red8[i];
        red8[0] = x;
    }
    __syncthreads();
    float r = red8[0];
    __syncthreads();
    return r;
}

// ---------------- att over body t + f_pun2body ----------------
__global__ void k_attB(){
    int b = blockIdx.x, tid = threadIdx.x;
    __shared__ float w[TBODY];
    __shared__ float red8[8];
    __shared__ float fs[2][128];
    float v0 = g_rowmax[b*TBODY + tid];
    float v1 = g_rowmax[b*TBODY + 256 + tid];
    float mx = block_reduce_max(fmaxf(v0, v1), red8, tid);
    float e0 = __expf(v0 - mx), e1 = __expf(v1 - mx);
    w[tid] = e0; w[256 + tid] = e1;
    float sum = block_reduce_sum(e0 + e1, red8, tid);
    float inv = 1.f/sum;
    int d = tid & 127, half = tid >> 7;
    const float* Mp = g_bodyM + ((size_t)(b*TBODY + half*256))*128 + d;
    float acc = 0.f;
    for (int t=0;t<256;t++) acc += w[half*256 + t]*Mp[(size_t)t*128];
    fs[half][d] = acc;
    __syncthreads();
    if (tid < 128) g_feat[b*256 + tid] = (fs[0][tid] + fs[1][tid])*inv;
}

// ---------------- att over pun p + f_body2pun ----------------
__global__ void k_attP(){
    int b = blockIdx.x, tid = threadIdx.x;
    __shared__ float w[TPUN];
    __shared__ float red8[8];
    __shared__ float fs[2][128];
    float v = funmap(g_colmax[b*TPUN + tid]) + g_Bp[b*TPUN + tid];
    float mx = block_reduce_max(v, red8, tid);
    float e = __expf(v - mx);
    w[tid] = e;
    float sum = block_reduce_sum(e, red8, tid);
    float inv = 1.f/sum;
    int d = tid & 127, half = tid >> 7;
    const float* Mp = g_punM + ((size_t)(b*TPUN + half*128))*128 + d;
    float acc = 0.f;
    for (int t=0;t<128;t++) acc += w[half*128 + t]*Mp[(size_t)t*128];
    fs[half][d] = acc;
    __syncthreads();
    if (tid < 128) g_feat[b*256 + 128 + tid] = (fs[0][tid] + fs[1][tid])*inv;
}

// ---------------- final head ----------------
__global__ void k_out(const float* __restrict__ Wd, const float* __restrict__ bd,
                      float* __restrict__ out){
    int b = blockIdx.x;
    int wj = threadIdx.x >> 5, lane = threadIdx.x & 31;
    if (wj >= 3) return;
    float s = 0.f;
    for (int k=lane;k<256;k+=32) s += g_feat[b*256 + k]*Wd[wj*256 + k];
    #pragma unroll
    for (int off=16;off;off>>=1) s += __shfl_xor_sync(0xffffffffu, s, off);
    if (lane == 0) out[b*3 + wj] = s + bd[wj];
}

// ---------------- launch ----------------
extern "C" void kernel_launch(void* const* d_in, const int* in_sizes, int n_in,
                              void* d_out, int out_size){
    const int*   body_idx = (const int*)  d_in[0];
    const int*   pun_idx  = (const int*)  d_in[1];
    const float* emb      = (const float*)d_in[2];
    const float *w_u, *Wd, *bd;
    const float *bWih_f,*bWhh_f,*bb_f,*bWih_b,*bWhh_b,*bb_b;
    const float *pWih_f,*pWhh_f,*pb_f,*pWih_b,*pWhh_b,*pb_b;
    if (in_sizes[3] == 384){
        w_u = (const float*)d_in[3]; Wd = (const float*)d_in[4]; bd = (const float*)d_in[5];
        bWih_f=(const float*)d_in[6];  bWhh_f=(const float*)d_in[7];  bb_f=(const float*)d_in[8];
        bWih_b=(const float*)d_in[9];  bWhh_b=(const float*)d_in[10]; bb_b=(const float*)d_in[11];
        pWih_f=(const float*)d_in[12]; pWhh_f=(const float*)d_in[13]; pb_f=(const float*)d_in[14];
        pWih_b=(const float*)d_in[15]; pWhh_b=(const float*)d_in[16]; pb_b=(const float*)d_in[17];
    } else {
        bWih_f=(const float*)d_in[3];  bWhh_f=(const float*)d_in[4];  bb_f=(const float*)d_in[5];
        bWih_b=(const float*)d_in[6];  bWhh_b=(const float*)d_in[7];  bb_b=(const float*)d_in[8];
        pWih_f=(const float*)d_in[9];  pWhh_f=(const float*)d_in[10]; pb_f=(const float*)d_in[11];
        pWih_b=(const float*)d_in[12]; pWhh_b=(const float*)d_in[13]; pb_b=(const float*)d_in[14];
        w_u=(const float*)d_in[15]; Wd=(const float*)d_in[16]; bd=(const float*)d_in[17];
    }
    float* out = (float*)d_out;

    k_zero<<<2048, 256>>>();
    k_lens<<<dim3(BB,2), 256>>>(body_idx, pun_idx);
    k_prep<<<(2*KP2*NC + 255)/256, 256>>>(bWih_f, bWih_b, pWih_f, pWih_b,
                                          bb_f, bb_b, pb_f, pb_b);
    k_gemm3<<<6144, 256>>>(body_idx, pun_idx, emb);
    k_scan<<<512, 256>>>(bWhh_f, bWhh_b, pWhh_f, pWhh_b);
    k_rowdots<<<(BB*TBODY + BB*TPUN)/8, 256>>>(w_u);
    k_align<<<dim3(TBODY/64, BB), 256>>>(w_u);
    k_attB<<<BB, 256>>>();
    k_attP<<<BB, 256>>>();
    k_out<<<BB, 96>>>(Wd, bd, out);
}

// round 17
// speedup vs baseline: 1.2427x; 1.2427x over previous
#include <cuda_runtime.h>
#include <cuda_bf16.h>
#include <cstdint>

#define BB    128
#define TBODY 512
#define TPUN  256
#define EMBD  300
#define HD    64
#define NG    256      // 4H gates per direction
#define NC    512      // both directions stacked
#define KP2   320      // K padded to multiple of 32 for bf16 MMA

typedef unsigned long long u64;
typedef unsigned int u32;

// ---------------- f32x2 packed-FMA helpers (FFMA2 via PTX) ----------------
__device__ __forceinline__ u64 pk2(float lo, float hi){
    u64 r; asm("mov.b64 %0, {%1,%2};" : "=l"(r) : "f"(lo), "f"(hi)); return r;
}
__device__ __forceinline__ float2 upk2(u64 v){
    float2 r; asm("mov.b64 {%0,%1}, %2;" : "=f"(r.x), "=f"(r.y) : "l"(v)); return r;
}
__device__ __forceinline__ u64 fma2(u64 a, u64 b, u64 c){
    u64 d; asm("fma.rn.f32x2 %0, %1, %2, %3;" : "=l"(d) : "l"(a), "l"(b), "l"(c)); return d;
}

// ---------------- MMA helpers ----------------
__device__ __forceinline__ u32 s2u(const void* p){
    return (u32)__cvta_generic_to_shared(p);
}
__device__ __forceinline__ void ldsm_x4(u32& r0, u32& r1, u32& r2, u32& r3, u32 addr){
    asm volatile("ldmatrix.sync.aligned.m8n8.x4.shared.b16 {%0,%1,%2,%3}, [%4];"
                 : "=r"(r0), "=r"(r1), "=r"(r2), "=r"(r3) : "r"(addr));
}
__device__ __forceinline__ void ldsm_x4t(u32& r0, u32& r1, u32& r2, u32& r3, u32 addr){
    asm volatile("ldmatrix.sync.aligned.m8n8.x4.trans.shared.b16 {%0,%1,%2,%3}, [%4];"
                 : "=r"(r0), "=r"(r1), "=r"(r2), "=r"(r3) : "r"(addr));
}
__device__ __forceinline__ void mma_bf16(float* c, const u32* a, const u32* b){
    asm volatile("mma.sync.aligned.m16n8k16.row.col.f32.bf16.bf16.f32 "
                 "{%0,%1,%2,%3}, {%4,%5,%6,%7}, {%8,%9}, {%0,%1,%2,%3};"
                 : "+f"(c[0]), "+f"(c[1]), "+f"(c[2]), "+f"(c[3])
                 : "r"(a[0]), "r"(a[1]), "r"(a[2]), "r"(a[3]), "r"(b[0]), "r"(b[1]));
}

// ---------------- scratch (static device globals; no allocation) ----------------
__device__ float          g_xp_body[(size_t)BB*TBODY*NC];
__device__ float          g_xp_pun [(size_t)BB*TPUN *NC];
__device__ __nv_bfloat16  g_Wth[2][(size_t)KP2*NC];   // Wih^T hi (k-major, zero-padded)
__device__ __nv_bfloat16  g_Wtl[2][(size_t)KP2*NC];   // Wih^T lo
__device__ float          g_biasv[2][NC];
__device__ int            g_lens[2][BB];
__device__ float          g_bodyM[(size_t)BB*TBODY*128];
__device__ float          g_punM [(size_t)BB*TPUN *128];
__device__ float          g_Ab[BB*TBODY];
__device__ float          g_Bp[BB*TPUN];
__device__ float          g_rowmax[BB*TBODY];
__device__ unsigned       g_colmax[BB*TPUN];
__device__ float          g_feat[BB*256];

// ---------------- helpers ----------------
__device__ __forceinline__ float sigm(float x){ return 1.f/(1.f + __expf(-x)); }
__device__ __forceinline__ float tanh_fast(float x){
    x = fminf(fmaxf(x, -15.f), 15.f);
    float t = __expf(2.f*x);
    return (t - 1.f)/(t + 1.f);
}
__device__ __forceinline__ unsigned fmap(float f){
    unsigned u = __float_as_uint(f);
    return (u & 0x80000000u) ? ~u : (u | 0x80000000u);
}
__device__ __forceinline__ float funmap(unsigned u){
    return (u & 0x80000000u) ? __uint_as_float(u ^ 0x80000000u) : __uint_as_float(~u);
}

// ---------------- zero-init of masked output buffers ----------------
__global__ void k_zero(){
    size_t i = (size_t)blockIdx.x*blockDim.x + threadIdx.x;
    size_t stride = (size_t)gridDim.x*blockDim.x;
    for (size_t k=i; k<(size_t)BB*TBODY*128; k+=stride) g_bodyM[k] = 0.f;
    for (size_t k=i; k<(size_t)BB*TPUN *128; k+=stride) g_punM [k] = 0.f;
    for (size_t k=i; k<(size_t)BB*TPUN;      k+=stride) g_colmax[k] = 0u;
}

// ---------------- sequence lengths ----------------
__global__ void k_lens(const int* __restrict__ body_idx, const int* __restrict__ pun_idx){
    int c = blockIdx.y, b = blockIdx.x;
    int T = c ? TPUN : TBODY;
    const int* a = (c ? pun_idx : body_idx) + (size_t)b*T;
    int tid = threadIdx.x;
    int cnt = 0;
    for (int t = tid; t < T; t += 256) cnt += (a[t] != 0);
    #pragma unroll
    for (int o=16;o;o>>=1) cnt += __shfl_xor_sync(0xffffffffu, cnt, o);
    __shared__ int sred[8];
    if ((tid & 31) == 0) sred[tid>>5] = cnt;
    __syncthreads();
    if (tid == 0){
        int s = 0;
        #pragma unroll
        for (int i=0;i<8;i++) s += sred[i];
        g_lens[c][b] = s;
    }
}

// ---------------- prepack Wih^T to bf16 hi/lo (k-major, zero-padded) + bias ------
__global__ void k_prep(const float* __restrict__ bWf, const float* __restrict__ bWb,
                       const float* __restrict__ pWf, const float* __restrict__ pWb,
                       const float* __restrict__ bbf, const float* __restrict__ bbb,
                       const float* __restrict__ pbf, const float* __restrict__ pbb){
    int gid = blockIdx.x*256 + threadIdx.x;
    const int tot = 2*KP2*NC;
    if (gid < tot){
        int c = gid / (KP2*NC);
        int r = gid % (KP2*NC);
        int k = r / NC, n = r % NC;
        float v = 0.f;
        if (k < EMBD){
            const float* W = c ? (n < NG ? pWf : pWb) : (n < NG ? bWf : bWb);
            v = W[(n & 255)*EMBD + k];
        }
        __nv_bfloat16 h = __float2bfloat16(v);
        __nv_bfloat16 l = __float2bfloat16(v - __bfloat162float(h));
        g_Wth[c][(size_t)k*NC + n] = h;
        g_Wtl[c][(size_t)k*NC + n] = l;
    }
    if (gid < 2*NC){
        int c = gid / NC, n = gid % NC;
        const float* bi = c ? (n < NG ? pbf : pbb) : (n < NG ? bbf : bbb);
        g_biasv[c][n] = bi[n & 255];
    }
}

// ---------------- gather + projection GEMM via mma.sync bf16 split --------------
// Block 128m x 64n. 8 warps as 4m x 2n; warp tile 32x32 = 2 m16 x 4 n8 mma tiles.
// acc = Ah*Bh + Ah*Bl + Al*Bh  (2-term split-bf16, fp32 accumulate)
// Software pipeline: register-prefetch of tile k+1 overlaps gather latency
// with the MMA compute of tile k.
__global__ __launch_bounds__(256,2) void k_gemm3(const int* __restrict__ body_idx,
                                                 const int* __restrict__ pun_idx,
                                                 const float* __restrict__ emb){
    __shared__ __align__(16) __nv_bfloat16 Ah[128][40];   // 32 k + pad 8
    __shared__ __align__(16) __nv_bfloat16 Al[128][40];
    __shared__ __align__(16) __nv_bfloat16 Bh[32][72];    // 64 n + pad 8
    __shared__ __align__(16) __nv_bfloat16 Bl[32][72];

    int bid = blockIdx.x;
    int corpus = (bid >= 4096);
    int local = corpus ? bid - 4096 : bid;
    int mt = local >> 3, nt = local & 7;
    int m0 = mt*128, n0 = nt*64;

    const int*   idx  = corpus ? pun_idx : body_idx;
    float*       out  = corpus ? g_xp_pun : g_xp_body;
    const __nv_bfloat16* WtH = g_Wth[corpus];
    const __nv_bfloat16* WtL = g_Wtl[corpus];
    const float* bias = g_biasv[corpus];

    int tid  = threadIdx.x;
    int lane = tid & 31, warp = tid >> 5;
    int warp_m = warp & 3, warp_n = warp >> 2;     // 4 x 2 warps
    int wm0 = warp_m*32, wn0 = warp_n*32;

    // A staging roles (coalesced): 4 passes of 32 rows; 8 threads x float4 per row
    int arow4 = tid >> 3;          // 0..31 (row within pass)
    int kq    = (tid & 7)*4;       // 0..28 (k offset within 32-k tile)
    const float* aptr[4];
    #pragma unroll
    for (int p=0;p<4;p++)
        aptr[p] = emb + (size_t)idx[m0 + p*32 + arow4]*EMBD + kq;

    // B staging roles
    int br = tid >> 3;              // B row (k) 0..31
    int bc = (tid & 7)*8;           // B col group (8 bf16)

    float acc[2][4][4];
    #pragma unroll
    for (int i=0;i<2;i++)
        #pragma unroll
        for (int j=0;j<4;j++)
            #pragma unroll
            for (int q=0;q<4;q++) acc[i][j][q] = 0.f;

    // prologue: prefetch tile 0 into registers
    float4 va[4];
    uint4 vbh, vbl;
    #pragma unroll
    for (int p=0;p<4;p++){
        const float* src = aptr[p];          // k0 = 0: kq+3 <= 31 < EMBD, no guard
        va[p] = *(const float4*)src;
    }
    {
        size_t src = (size_t)br*NC + n0 + bc;
        vbh = *(const uint4*)&WtH[src];
        vbl = *(const uint4*)&WtL[src];
    }

    for (int k0=0; k0<KP2; k0+=32){
        // store current registers to smem (A with bf16 hi/lo conversion)
        #pragma unroll
        for (int p=0;p<4;p++){
            int row = p*32 + arow4;
            float4 v = va[p];
            __nv_bfloat16 h0=__float2bfloat16(v.x), h1=__float2bfloat16(v.y);
            __nv_bfloat16 h2=__float2bfloat16(v.z), h3=__float2bfloat16(v.w);
            __nv_bfloat162 hh0=__halves2bfloat162(h0,h1);
            __nv_bfloat162 hh1=__halves2bfloat162(h2,h3);
            __nv_bfloat162 ll0=__halves2bfloat162(
                __float2bfloat16(v.x-__bfloat162float(h0)),
                __float2bfloat16(v.y-__bfloat162float(h1)));
            __nv_bfloat162 ll1=__halves2bfloat162(
                __float2bfloat16(v.z-__bfloat162float(h2)),
                __float2bfloat16(v.w-__bfloat162float(h3)));
            *(uint2*)&Ah[row][kq] = make_uint2(*(u32*)&hh0, *(u32*)&hh1);
            *(uint2*)&Al[row][kq] = make_uint2(*(u32*)&ll0, *(u32*)&ll1);
        }
        *(uint4*)&Bh[br][bc] = vbh;
        *(uint4*)&Bl[br][bc] = vbl;
        __syncthreads();

        // prefetch tile k0+32 (loads in flight across the compute below)
        int k1 = k0 + 32;
        if (k1 < KP2){
            #pragma unroll
            for (int p=0;p<4;p++){
                const float* src = aptr[p] + k1;
                float4 v;
                if (k1 + kq + 3 < EMBD){
                    v = *(const float4*)src;
                } else {
                    v.x = (k1+kq   < EMBD) ? src[0] : 0.f;
                    v.y = (k1+kq+1 < EMBD) ? src[1] : 0.f;
                    v.z = (k1+kq+2 < EMBD) ? src[2] : 0.f;
                    v.w = (k1+kq+3 < EMBD) ? src[3] : 0.f;
                }
                va[p] = v;
            }
            size_t src = (size_t)(k1 + br)*NC + n0 + bc;
            vbh = *(const uint4*)&WtH[src];
            vbl = *(const uint4*)&WtL[src];
        }

        // compute on the staged tile
        #pragma unroll
        for (int ks=0; ks<2; ks++){
            int kb = ks*16;
            // A fragments (hi & lo) for 2 m-tiles
            u32 ah[2][4], al[2][4];
            int arowf = (lane & 15);
            int acolf = kb + ((lane >> 4) << 3);
            #pragma unroll
            for (int mi=0; mi<2; mi++){
                u32 aAddrH = s2u(&Ah[wm0 + mi*16 + arowf][acolf]);
                ldsm_x4(ah[mi][0], ah[mi][1], ah[mi][2], ah[mi][3], aAddrH);
                u32 aAddrL = s2u(&Al[wm0 + mi*16 + arowf][acolf]);
                ldsm_x4(al[mi][0], al[mi][1], al[mi][2], al[mi][3], aAddrL);
            }
            // B fragments (hi & lo) for 4 n-tiles (2 per ldmatrix.x4.trans)
            u32 bh[4][2], bl[4][2];
            int bkrow = kb + (lane & 15);
            #pragma unroll
            for (int nh=0; nh<2; nh++){
                int bncol = wn0 + nh*16 + ((lane & 16) ? 8 : 0);
                u32 r0,r1,r2,r3;
                ldsm_x4t(r0, r1, r2, r3, s2u(&Bh[bkrow][bncol]));
                bh[2*nh][0]=r0; bh[2*nh][1]=r1; bh[2*nh+1][0]=r2; bh[2*nh+1][1]=r3;
                ldsm_x4t(r0, r1, r2, r3, s2u(&Bl[bkrow][bncol]));
                bl[2*nh][0]=r0; bl[2*nh][1]=r1; bl[2*nh+1][0]=r2; bl[2*nh+1][1]=r3;
            }
            // 2-term split: hh + hl + lh
            #pragma unroll
            for (int mi=0; mi<2; mi++)
                #pragma unroll
                for (int ni=0; ni<4; ni++){
                    mma_bf16(acc[mi][ni], ah[mi], bh[ni]);
                    mma_bf16(acc[mi][ni], ah[mi], bl[ni]);
                    mma_bf16(acc[mi][ni], al[mi], bh[ni]);
                }
        }
        __syncthreads();
    }

    // epilogue: bias + store (c0,c1 -> row r4; c2,c3 -> row r4+8)
    int r4 = lane >> 2, c2 = (lane & 3)*2;
    #pragma unroll
    for (int mi=0; mi<2; mi++){
        #pragma unroll
        for (int ni=0; ni<4; ni++){
            int n = n0 + wn0 + ni*8 + c2;
            float b0 = bias[n], b1 = bias[n+1];
            int m = m0 + wm0 + mi*16 + r4;
            float2 o0 = make_float2(acc[mi][ni][0] + b0, acc[mi][ni][1] + b1);
            float2 o1 = make_float2(acc[mi][ni][2] + b0, acc[mi][ni][3] + b1);
            *(float2*)&out[(size_t)m*NC + n]       = o0;
            *(float2*)&out[(size_t)(m+8)*NC + n]   = o1;
        }
    }
}

// ---------------- LSTM recurrence: 1 block per (corpus,batch,dir), f32x2 dots ----
__global__ __launch_bounds__(256) void k_scan(const float* __restrict__ bWhhf,
                                              const float* __restrict__ bWhhb,
                                              const float* __restrict__ pWhhf,
                                              const float* __restrict__ pWhhb){
    int bid = blockIdx.x;
    int corpus = bid >> 8;
    int b   = (bid & 255) >> 1;
    int dir = bid & 1;
    int T   = corpus ? TPUN : TBODY;
    int len = g_lens[corpus][b];
    const float* Whh = corpus ? (dir ? pWhhb : pWhhf) : (dir ? bWhhb : bWhhf);
    const float* xp  = corpus ? g_xp_pun : g_xp_body;
    float* M         = corpus ? g_punM   : g_bodyM;

    int tid = threadIdx.x;
    int j = tid >> 2, ssub = tid & 3;

    u64 Wr2[4][8];
    #pragma unroll
    for (int q=0;q<4;q++){
        const u64* wp = (const u64*)(Whh + (size_t)(q*64 + j)*64 + ssub*16);
        #pragma unroll
        for (int kk=0;kk<8;kk++) Wr2[q][kk] = wp[kk];
    }

    __shared__ __align__(16) float hbuf[2][64];
    __shared__ float xps[2][256];
    if (tid < 64) hbuf[0][tid] = 0.f;
    if (len > 0){
        int r0 = b*T + (dir ? (len-1) : 0);
        xps[0][tid] = xp[(size_t)r0*NC + dir*NG + tid];
    }
    __syncthreads();

    float c = 0.f;
    for (int s=0; s<len; s++){
        int cur = s & 1;
        float xn = 0.f;
        if (s+1 < len){
            int t1 = dir ? (len-2-s) : (s+1);
            xn = xp[(size_t)(b*T + t1)*NC + dir*NG + tid];
        }
        ulonglong2 hq0 = *(const ulonglong2*)&hbuf[cur][ssub*16];
        ulonglong2 hq1 = *(const ulonglong2*)&hbuf[cur][ssub*16+4];
        ulonglong2 hq2 = *(const ulonglong2*)&hbuf[cur][ssub*16+8];
        ulonglong2 hq3 = *(const ulonglong2*)&hbuf[cur][ssub*16+12];
        u64 h2[8] = {hq0.x,hq0.y,hq1.x,hq1.y,hq2.x,hq2.y,hq3.x,hq3.y};
        u64 s0=0ull, s1=0ull, s2=0ull, s3=0ull;
        #pragma unroll
        for (int kk=0;kk<8;kk++){
            s0 = fma2(h2[kk], Wr2[0][kk], s0);
            s1 = fma2(h2[kk], Wr2[1][kk], s1);
            s2 = fma2(h2[kk], Wr2[2][kk], s2);
            s3 = fma2(h2[kk], Wr2[3][kk], s3);
        }
        float2 f0=upk2(s0), f1=upk2(s1), f2=upk2(s2), f3=upk2(s3);
        float a0=f0.x+f0.y, a1=f1.x+f1.y, a2=f2.x+f2.y, a3=f3.x+f3.y;
        #pragma unroll
        for (int o=1;o<=2;o<<=1){
            a0 += __shfl_xor_sync(0xffffffffu, a0, o);
            a1 += __shfl_xor_sync(0xffffffffu, a1, o);
            a2 += __shfl_xor_sync(0xffffffffu, a2, o);
            a3 += __shfl_xor_sync(0xffffffffu, a3, o);
        }
        float gi = sigm     (a0 + xps[cur][      j]);
        float gf = sigm     (a1 + xps[cur][ 64 + j]);
        float gg = tanh_fast(a2 + xps[cur][128 + j]);
        float go = sigm     (a3 + xps[cur][192 + j]);
        c = gf*c + gi*gg;
        float hn = go * tanh_fast(c);
        if (ssub == 0){
            hbuf[cur^1][j] = hn;
            int tout = dir ? (len-1-s) : s;
            M[((size_t)(b*T + tout))*128 + dir*64 + j] = hn;
        }
        xps[cur^1][tid] = xn;
        __syncthreads();
    }
}

// ---------------- row dots: A[t]=body_M.w1, Bv[p]=pun_M.w2 (1 warp per row) ----------------
__global__ void k_rowdots(const float* __restrict__ wu){
    int gwarp = (blockIdx.x*256 + threadIdx.x) >> 5;
    int lane  = threadIdx.x & 31;
    const float* M; const float* w; float* o;
    if (gwarp < BB*TBODY){
        M = g_bodyM + (size_t)gwarp*128; w = wu;       o = g_Ab + gwarp;
    } else {
        int r = gwarp - BB*TBODY;
        if (r >= BB*TPUN) return;
        M = g_punM  + (size_t)r*128;     w = wu + 128; o = g_Bp + r;
    }
    float s = 0.f;
    #pragma unroll
    for (int i=0;i<4;i++) s += M[lane + 32*i]*w[lane + 32*i];
    #pragma unroll
    for (int off=16;off;off>>=1) s += __shfl_xor_sync(0xffffffffu, s, off);
    if (lane == 0) *o = s;
}

// ---------------- alignment maxes: 64t x 256p tile, k-major body, quad-split p --
__global__ __launch_bounds__(256) void k_align(const float* __restrict__ wu){
    __shared__ __align__(16) float bst[16][68];   // body chunk, k-major (x w3)
    __shared__ __align__(16) float ps[16][256];   // pun k-chunk; reused as colred
    __shared__ float As_[64];
    __shared__ float Bps[256];
    int b = blockIdx.y;
    int t0 = blockIdx.x*64;
    int tid = threadIdx.x;
    int ty = tid >> 5, tx = tid & 31;

    if (tid < 64) As_[tid] = g_Ab[b*TBODY + t0 + tid];
    Bps[tid] = g_Bp[b*TPUN + tid];

    u64 acc2[8][4];
    #pragma unroll
    for (int i=0;i<8;i++)
        #pragma unroll
        for (int j=0;j<4;j++) acc2[i][j] = 0ull;

    for (int kc=0;kc<128;kc+=16){
        __syncthreads();
        {   // stage pun chunk (transposed: ps[k][p])
            const float* src = g_punM + ((size_t)(b*TPUN + tid))*128 + kc;
            float4 v0 = *(const float4*)(src   );
            float4 v1 = *(const float4*)(src+ 4);
            float4 v2 = *(const float4*)(src+ 8);
            float4 v3 = *(const float4*)(src+12);
            ps[ 0][tid]=v0.x; ps[ 1][tid]=v0.y; ps[ 2][tid]=v0.z; ps[ 3][tid]=v0.w;
            ps[ 4][tid]=v1.x; ps[ 5][tid]=v1.y; ps[ 6][tid]=v1.z; ps[ 7][tid]=v1.w;
            ps[ 8][tid]=v2.x; ps[ 9][tid]=v2.y; ps[10][tid]=v2.z; ps[11][tid]=v2.w;
            ps[12][tid]=v3.x; ps[13][tid]=v3.y; ps[14][tid]=v3.z; ps[15][tid]=v3.w;
        }
        {   // stage body chunk k-major (x w3): bst[k][t]
            int t = tid >> 2, kq2 = (tid & 3)*4;
            const float* src = g_bodyM + ((size_t)(b*TBODY + t0 + t))*128 + kc + kq2;
            float4 v = *(const float4*)src;
            v.x *= wu[256+kc+kq2];   v.y *= wu[256+kc+kq2+1];
            v.z *= wu[256+kc+kq2+2]; v.w *= wu[256+kc+kq2+3];
            bst[kq2  ][t] = v.x; bst[kq2+1][t] = v.y;
            bst[kq2+2][t] = v.z; bst[kq2+3][t] = v.w;
        }
        __syncthreads();
        #pragma unroll
        for (int kk=0;kk<16;kk++){
            float4 tv0 = *(const float4*)&bst[kk][ty*8];
            float4 tv1 = *(const float4*)&bst[kk][ty*8+4];
            ulonglong2 p0 = *(const ulonglong2*)&ps[kk][tx*4];
            ulonglong2 p1 = *(const ulonglong2*)&ps[kk][tx*4+128];
            u64 p2[4] = {p0.x, p0.y, p1.x, p1.y};
            float tv[8] = {tv0.x,tv0.y,tv0.z,tv0.w, tv1.x,tv1.y,tv1.z,tv1.w};
            #pragma unroll
            for (int it=0;it<8;it++){
                u64 ar = pk2(tv[it], tv[it]);
                #pragma unroll
                for (int c=0;c<4;c++) acc2[it][c] = fma2(ar, p2[c], acc2[it][c]);
            }
        }
    }
    float Bloc[8];
    #pragma unroll
    for (int q=0;q<4;q++){ Bloc[q] = Bps[tx*4+q]; Bloc[4+q] = Bps[tx*4+128+q]; }
    #pragma unroll
    for (int it=0;it<8;it++){
        float m = -3.4e38f;
        #pragma unroll
        for (int jj=0;jj<4;jj++){
            float2 v = upk2(acc2[it][jj]);
            m = fmaxf(m, v.x + Bloc[2*jj]);
            m = fmaxf(m, v.y + Bloc[2*jj+1]);
        }
        #pragma unroll
        for (int off=16;off;off>>=1) m = fmaxf(m, __shfl_xor_sync(0xffffffffu, m, off));
        if (tx == 0) g_rowmax[b*TBODY + t0 + ty*8 + it] = As_[ty*8+it] + m;
    }
    __syncthreads();
    float (*colred)[256] = (float(*)[256])ps;
    #pragma unroll
    for (int jj=0;jj<4;jj++){
        float mx_lo = -3.4e38f, mx_hi = -3.4e38f;
        #pragma unroll
        for (int it=0;it<8;it++){
            float2 v = upk2(acc2[it][jj]);
            mx_lo = fmaxf(mx_lo, v.x + As_[ty*8+it]);
            mx_hi = fmaxf(mx_hi, v.y + As_[ty*8+it]);
        }
        int pl = (jj < 2) ? (tx*4 + 2*jj) : (tx*4 + 128 + 2*(jj-2));
        colred[ty][pl    ] = mx_lo;
        colred[ty][pl + 1] = mx_hi;
    }
    __syncthreads();
    {
        float m = colred[0][tid];
        #pragma unroll
        for (int r=1;r<8;r++) m = fmaxf(m, colred[r][tid]);
        atomicMax(&g_colmax[b*TPUN + tid], fmap(m));
    }
}

// ---------------- block reduce helpers via smem ----------------
__device__ __forceinline__ float block_reduce_max(float v, float* red8, int tid){
    #pragma unroll
    for (int o=16;o;o>>=1) v = fmaxf(v, __shfl_xor_sync(0xffffffffu, v, o));
    if ((tid & 31) == 0) red8[tid>>5] = v;
    __syncthreads();
    if (tid == 0){
        float x = red8[0];
        #pragma unroll
        for (int i=1;i<8;i++) x = fmaxf(x, red8[i]);
        red8[0] = x;
    }
    __syncthreads();
    float r = red8[0];
    __syncthreads();
    return r;
}
__device__ __forceinline__ float block_reduce_sum(float v, float* red8, int tid){
    #pragma unroll
    for (int o=16;o;o>>=1) v += __shfl_xor_sync(0xffffffffu, v, o);
    if ((tid & 31) == 0) red8[tid>>5] = v;
    __syncthreads();
    if (tid == 0){
        float x = 0.f;
        #pragma unroll
        for (int i=0;i<8;i++) x += red8[i];
        red8[0] = x;
    }
    __syncthreads();
    float r = red8[0];
    __syncthreads();
    return r;
}

// ---------------- att over body t + f_pun2body ----------------
__global__ void k_attB(){
    int b = blockIdx.x, tid = threadIdx.x;
    __shared__ float w[TBODY];
    __shared__ float red8[8];
    __shared__ float fs[2][128];
    float v0 = g_rowmax[b*TBODY + tid];
    float v1 = g_rowmax[b*TBODY + 256 + tid];
    float mx = block_reduce_max(fmaxf(v0, v1), red8, tid);
    float e0 = __expf(v0 - mx), e1 = __expf(v1 - mx);
    w[tid] = e0; w[256 + tid] = e1;
    float sum = block_reduce_sum(e0 + e1, red8, tid);
    float inv = 1.f/sum;
    int d = tid & 127, half = tid >> 7;
    const float* Mp = g_bodyM + ((size_t)(b*TBODY + half*256))*128 + d;
    float acc = 0.f;
    for (int t=0;t<256;t++) acc += w[half*256 + t]*Mp[(size_t)t*128];
    fs[half][d] = acc;
    __syncthreads();
    if (tid < 128) g_feat[b*256 + tid] = (fs[0][tid] + fs[1][tid])*inv;
}

// ---------------- att over pun p + f_body2pun ----------------
__global__ void k_attP(){
    int b = blockIdx.x, tid = threadIdx.x;
    __shared__ float w[TPUN];
    __shared__ float red8[8];
    __shared__ float fs[2][128];
    float v = funmap(g_colmax[b*TPUN + tid]) + g_Bp[b*TPUN + tid];
    float mx = block_reduce_max(v, red8, tid);
    float e = __expf(v - mx);
    w[tid] = e;
    float sum = block_reduce_sum(e, red8, tid);
    float inv = 1.f/sum;
    int d = tid & 127, half = tid >> 7;
    const float* Mp = g_punM + ((size_t)(b*TPUN + half*128))*128 + d;
    float acc = 0.f;
    for (int t=0;t<128;t++) acc += w[half*128 + t]*Mp[(size_t)t*128];
    fs[half][d] = acc;
    __syncthreads();
    if (tid < 128) g_feat[b*256 + 128 + tid] = (fs[0][tid] + fs[1][tid])*inv;
}

// ---------------- final head ----------------
__global__ void k_out(const float* __restrict__ Wd, const float* __restrict__ bd,
                      float* __restrict__ out){
    int b = blockIdx.x;
    int wj = threadIdx.x >> 5, lane = threadIdx.x & 31;
    if (wj >= 3) return;
    float s = 0.f;
    for (int k=lane;k<256;k+=32) s += g_feat[b*256 + k]*Wd[wj*256 + k];
    #pragma unroll
    for (int off=16;off;off>>=1) s += __shfl_xor_sync(0xffffffffu, s, off);
    if (lane == 0) out[b*3 + wj] = s + bd[wj];
}

// ---------------- launch ----------------
extern "C" void kernel_launch(void* const* d_in, const int* in_sizes, int n_in,
                              void* d_out, int out_size){
    const int*   body_idx = (const int*)  d_in[0];
    const int*   pun_idx  = (const int*)  d_in[1];
    const float* emb      = (const float*)d_in[2];
    const float *w_u, *Wd, *bd;
    const float *bWih_f,*bWhh_f,*bb_f,*bWih_b,*bWhh_b,*bb_b;
    const float *pWih_f,*pWhh_f,*pb_f,*pWih_b,*pWhh_b,*pb_b;
    if (in_sizes[3] == 384){
        w_u = (const float*)d_in[3]; Wd = (const float*)d_in[4]; bd = (const float*)d_in[5];
        bWih_f=(const float*)d_in[6];  bWhh_f=(const float*)d_in[7];  bb_f=(const float*)d_in[8];
        bWih_b=(const float*)d_in[9];  bWhh_b=(const float*)d_in[10]; bb_b=(const float*)d_in[11];
        pWih_f=(const float*)d_in[12]; pWhh_f=(const float*)d_in[13]; pb_f=(const float*)d_in[14];
        pWih_b=(const float*)d_in[15]; pWhh_b=(const float*)d_in[16]; pb_b=(const float*)d_in[17];
    } else {
        bWih_f=(const float*)d_in[3];  bWhh_f=(const float*)d_in[4];  bb_f=(const float*)d_in[5];
        bWih_b=(const float*)d_in[6];  bWhh_b=(const float*)d_in[7];  bb_b=(const float*)d_in[8];
        pWih_f=(const float*)d_in[9];  pWhh_f=(const float*)d_in[10]; pb_f=(const float*)d_in[11];
        pWih_b=(const float*)d_in[12]; pWhh_b=(const float*)d_in[13]; pb_b=(const float*)d_in[14];
        w_u=(const float*)d_in[15]; Wd=(const float*)d_in[16]; bd=(const float*)d_in[17];
    }
    float* out = (float*)d_out;

    k_zero<<<2048, 256>>>();
    k_lens<<<dim3(BB,2), 256>>>(body_idx, pun_idx);
    k_prep<<<(2*KP2*NC + 255)/256, 256>>>(bWih_f, bWih_b, pWih_f, pWih_b,
                                          bb_f, bb_b, pb_f, pb_b);
    k_gemm3<<<6144, 256>>>(body_idx, pun_idx, emb);
    k_scan<<<512, 256>>>(bWhh_f, bWhh_b, pWhh_f, pWhh_b);
    k_rowdots<<<(BB*TBODY + BB*TPUN)/8, 256>>>(w_u);
    k_align<<<dim3(TBODY/64, BB), 256>>>(w_u);
    k_attB<<<BB, 256>>>();
    k_attP<<<BB, 256>>>();
    k_out<<<BB, 96>>>(Wd, bd, out);
}